// round 11
// baseline (speedup 1.0000x reference)
#include <cuda_runtime.h>
#include <cuda_bf16.h>
#include <math.h>
#include <stdint.h>

#define N_NODES 97
#define IN_T    12
#define HID     6
#define NG      24
#define FULLM   0xffffffffu
#define SEG     256
#define WARM    128
#define MAXT    16384

typedef unsigned long long ull;
typedef unsigned short u16;

// GEMM geometry: block tile M=128 x N(t)=64, K chunk 64.
// conv1: K=582 -> Kpad 640 (KCH=10),  M=1164 -> 10 m-tiles
// conv2: K=1164 -> Kpad 1216 (KCH=19), M=1164 -> 10 m-tiles
// conv3: K=1164 -> Kpad 1216 (KCH=19), M=582 -> 5 m-tiles
#define K1PAD 640
#define K2PAD 1216

// ---------------- device globals ---------------------------------------------------
__device__ float4 g_xp4[MAXT * N_NODES * HID];      // (t,n,unit)->(i,f,g,o); i,f,o *0.5
__device__ u16    g_b0h[MAXT * K1PAD];              // LSTM h, bf16 hi  [t, ci*6+hh]
__device__ u16    g_b0l[MAXT * K1PAD];              // bf16 lo
__device__ u16    g_f1h[MAXT * K2PAD];
__device__ u16    g_f1l[MAXT * K2PAD];
__device__ u16    g_f2h[MAXT * K2PAD];
__device__ u16    g_f2l[MAXT * K2PAD];
__device__ float  g_f3 [MAXT * K1PAD];              // conv3 out fp32 [t, n*6+h] stride 640
__device__ u16    g_a1h[1280 * K1PAD];              // A' band matrices, bf16 hi/lo
__device__ u16    g_a1l[1280 * K1PAD];
__device__ u16    g_a2h[1280 * K2PAD];
__device__ u16    g_a2l[1280 * K2PAD];
__device__ u16    g_a3h[640 * K2PAD];
__device__ u16    g_a3l[640 * K2PAD];
__device__ float  g_scale[N_NODES];
__device__ float  g_shift[N_NODES];
__device__ double g_sumd[N_NODES];
__device__ double g_sqd [N_NODES];

// ---------------- small helpers ----------------------------------------------------
__device__ __forceinline__ float tanha(float x) {
    float y; asm("tanh.approx.f32 %0, %1;" : "=f"(y) : "f"(x)); return y;
}
__device__ __forceinline__ ull pk(float lo, float hi) {
    ull r; asm("mov.b64 %0, {%1, %2};" : "=l"(r) : "f"(lo), "f"(hi)); return r;
}
__device__ __forceinline__ void unpk(float& lo, float& hi, ull v) {
    asm("mov.b64 {%0, %1}, %2;" : "=f"(lo), "=f"(hi) : "l"(v));
}
__device__ __forceinline__ void fma2(ull& d, ull a, ull b) {
    asm("fma.rn.f32x2 %0, %1, %2, %0;" : "+l"(d) : "l"(a), "l"(b));
}
__device__ __forceinline__ ull mul2(ull a, ull b) {
    ull d; asm("mul.rn.f32x2 %0, %1, %2;" : "=l"(d) : "l"(a), "l"(b)); return d;
}
__device__ __forceinline__ ull add2(ull a, ull b) {
    ull d; asm("add.rn.f32x2 %0, %1, %2;" : "=l"(d) : "l"(a), "l"(b)); return d;
}
__device__ __forceinline__ void bsplit(float x, u16& h, u16& l) {
    __nv_bfloat16 bh = __float2bfloat16_rn(x);
    float r = x - __bfloat162float(bh);
    h = __bfloat16_as_ushort(bh);
    l = __bfloat16_as_ushort(__float2bfloat16_rn(r));
}
__device__ __forceinline__ uint32_t smem_u32(const void* p) {
    uint32_t a;
    asm("{ .reg .u64 t; cvta.to.shared.u64 t, %1; cvt.u32.u64 %0, t; }" : "=r"(a) : "l"(p));
    return a;
}
#define SWZ(x) ((x) ^ (((x) >> 3) & 0x70))

__device__ __forceinline__ void ldsm4(uint32_t* r, uint32_t addr) {
    asm volatile("ldmatrix.sync.aligned.m8n8.x4.shared.b16 {%0,%1,%2,%3}, [%4];"
        : "=r"(r[0]), "=r"(r[1]), "=r"(r[2]), "=r"(r[3]) : "r"(addr));
}
__device__ __forceinline__ void mma_bf16(float* d, const uint32_t* a,
                                         uint32_t b0, uint32_t b1) {
    asm volatile("mma.sync.aligned.m16n8k16.row.col.f32.bf16.bf16.f32 "
        "{%0,%1,%2,%3}, {%4,%5,%6,%7}, {%8,%9}, {%0,%1,%2,%3};"
        : "+f"(d[0]), "+f"(d[1]), "+f"(d[2]), "+f"(d[3])
        : "r"(a[0]), "r"(a[1]), "r"(a[2]), "r"(a[3]), "r"(b0), "r"(b1));
}

// ---------------- prep: A' band matrices (hi/lo) + BN reset ------------------------
__global__ void prep_all(const float* __restrict__ Wc1,
                         const float* __restrict__ Wc2,
                         const float* __restrict__ Wc3) {
    int idx = blockIdx.x * 256 + threadIdx.x;
    if (idx < N_NODES) { g_sumd[idx] = 0.0; g_sqd[idx] = 0.0; }

    if (idx < 1280 * K2PAD) {           // A2 [1280 x 1216]
        int m = idx / K2PAD, k = idx - m * K2PAD;
        float v = 0.f;
        if (m < 1164 && k < 1164) {
            int co = m / 6, h = m - co * 6, ci = k / 6, hh = k - ci * 6;
            int kh = hh - h + 1;
            if (kh >= 0 && kh < 3) v = Wc2[((co * 194 + ci) * 3 + kh) * 3 + 1];
        }
        bsplit(v, g_a2h[idx], g_a2l[idx]);
    }
    if (idx < 1280 * K1PAD) {           // A1 [1280 x 640]
        int m = idx / K1PAD, k = idx - m * K1PAD;
        float v = 0.f;
        if (m < 1164 && k < 582) {
            int co = m / 6, h = m - co * 6, ci = k / 6, hh = k - ci * 6;
            int kh = hh - h + 1;
            if (kh >= 0 && kh < 3) v = Wc1[((co * 97 + ci) * 3 + kh) * 3 + 1];
        }
        bsplit(v, g_a1h[idx], g_a1l[idx]);
    }
    if (idx < 640 * K2PAD) {            // A3 [640 x 1216]
        int m = idx / K2PAD, k = idx - m * K2PAD;
        float v = 0.f;
        if (m < 582 && k < 1164) {
            int co = m / 6, h = m - co * 6, ci = k / 6, hh = k - ci * 6;
            int kh = hh - h + 1;
            if (kh >= 0 && kh < 3) v = Wc3[((co * 194 + ci) * 3 + kh) * 3 + 1];
        }
        bsplit(v, g_a3h[idx], g_a3l[idx]);
    }
}

// ---------------- x-projection ------------------------------------------------------
__global__ void xproj_kernel(const float* __restrict__ X,
                             const float* __restrict__ W_ih,
                             const float* __restrict__ b_ih,
                             const float* __restrict__ b_hh,
                             int TN) {
    __shared__ float sw[NG * IN_T];
    __shared__ float sb[NG];
    int tid = threadIdx.x;
    if (tid < NG * IN_T) sw[tid] = W_ih[tid];
    if (tid < NG)        sb[tid] = b_ih[tid] + b_hh[tid];
    __syncthreads();
    int r = blockIdx.x * blockDim.x + tid;
    if (r >= TN) return;
    const float4* xp4 = reinterpret_cast<const float4*>(X + (size_t)r * IN_T);
    float4 a = xp4[0], b = xp4[1], c = xp4[2];
    float x[IN_T] = {a.x,a.y,a.z,a.w, b.x,b.y,b.z,b.w, c.x,c.y,c.z,c.w};
    float acc[NG];
    #pragma unroll
    for (int g = 0; g < NG; g++) {
        float s = sb[g];
        #pragma unroll
        for (int f = 0; f < IN_T; f++) s = fmaf(sw[g * IN_T + f], x[f], s);
        acc[g] = (g < 12 || g >= 18) ? 0.5f * s : s;
    }
    float4* out = g_xp4 + (size_t)r * HID;
    #pragma unroll
    for (int j = 0; j < HID; j++)
        out[j] = make_float4(acc[j], acc[6 + j], acc[12 + j], acc[18 + j]);
}

// ---------------- segmented-parallel LSTM scan (outputs bf16 hi/lo) ----------------
__global__ __launch_bounds__(128)
void lstm_seg(const float* __restrict__ W_hh, int T) {
    const int wid  = threadIdx.x >> 5;
    const int lane = threadIdx.x & 31;
    const int seg  = blockIdx.x / 5;
    const int wb   = blockIdx.x % 5;
    const int gw   = wb * 4 + wid;
    int grp = lane / 6;
    int j   = lane - grp * 6;
    bool valid = grp < 5;
    int node = gw * 5 + (valid ? grp : 0);
    if (node >= N_NODES) { node = 0; valid = false; }

    const int t_out0 = seg * SEG;
    if (t_out0 >= T) return;
    const int t_start = (t_out0 >= WARM) ? (t_out0 - WARM) : 0;
    const int t_end   = (t_out0 + SEG < T) ? (t_out0 + SEG) : T;

    ull wif[HID], wgo[HID];
    #pragma unroll
    for (int k = 0; k < HID; k++) {
        wif[k] = pk(0.5f * W_hh[(j)      * HID + k], 0.5f * W_hh[(6 + j)  * HID + k]);
        wgo[k] = pk(       W_hh[(12 + j) * HID + k], 0.5f * W_hh[(18 + j) * HID + k]);
    }

    const ulonglong2* xp = reinterpret_cast<const ulonglong2*>(g_xp4)
                           + (size_t)node * HID + j;
    const int STR = N_NODES * HID;
    const int PF = 4;
    ulonglong2 buf[PF];
    #pragma unroll
    for (int p = 0; p < PF; p++) {
        int tt = t_start + p;
        buf[p] = (tt < t_end) ? xp[(size_t)tt * STR] : make_ulonglong2(0, 0);
    }

    ull hp0, hp1, hp2, hp3, hp4, hp5;
    hp0 = hp1 = hp2 = hp3 = hp4 = hp5 = pk(0.f, 0.f);
    float c = 0.f;
    const int col = node * 6 + j;
    const int base = grp * 6;

    for (int tb = t_start; tb < t_end; tb += PF) {
        #pragma unroll
        for (int u = 0; u < PF; u++) {
            int t = tb + u;
            ulonglong2 xv = buf[u];
            int tp = t + PF;
            if (tp < t_end) buf[u] = xp[(size_t)tp * STR];

            ull s0 = xv.x;
            fma2(s0, wif[0], hp0); fma2(s0, wif[1], hp1); fma2(s0, wif[2], hp2);
            ull s1 = mul2(wif[3], hp3);
            fma2(s1, wif[4], hp4); fma2(s1, wif[5], hp5);
            s0 = add2(s0, s1);

            ull q0 = xv.y;
            fma2(q0, wgo[0], hp0); fma2(q0, wgo[1], hp1); fma2(q0, wgo[2], hp2);
            ull q1 = mul2(wgo[3], hp3);
            fma2(q1, wgo[4], hp4); fma2(q1, wgo[5], hp5);
            q0 = add2(q0, q1);

            float aI, aF, aG, aO;
            unpk(aI, aF, s0);
            unpk(aG, aO, q0);

            float fv = fmaf(tanha(aF), 0.5f, 0.5f);
            float iv = fmaf(tanha(aI), 0.5f, 0.5f);
            float gv = tanha(aG);
            float ov = fmaf(tanha(aO), 0.5f, 0.5f);

            c = fmaf(fv, c, iv * gv);
            float tc = tanha(c);
            float hn = tanha(ov * tc);

            if (valid && t >= t_out0 && t < t_end) {
                u16 hs, ls;
                bsplit(hn, hs, ls);
                g_b0h[(size_t)t * K1PAD + col] = hs;
                g_b0l[(size_t)t * K1PAD + col] = ls;
            }

            float h0 = __shfl_sync(FULLM, hn, base);
            float h1 = __shfl_sync(FULLM, hn, base + 1);
            float h2 = __shfl_sync(FULLM, hn, base + 2);
            float h3 = __shfl_sync(FULLM, hn, base + 3);
            float h4 = __shfl_sync(FULLM, hn, base + 4);
            float h5 = __shfl_sync(FULLM, hn, base + 5);
            hp0 = pk(h0, h0); hp1 = pk(h1, h1); hp2 = pk(h2, h2);
            hp3 = pk(h3, h3); hp4 = pk(h4, h4); hp5 = pk(h5, h5);
        }
    }
}

// ---------------- HMMA GEMM conv layer ---------------------------------------------
// D[m, t] = sum_k A'[m,k] B[t,k]; 3 split passes (AhBh, AhBl, AlBh), fp32 reg accum.
// MODE 0: out = relu(D+bias) -> bf16 hi/lo (stride K2PAD); MODE 1: fp32 (stride K1PAD)
template<int KCH, int MODE>
__global__ __launch_bounds__(256)
void gemm_conv(const u16* __restrict__ Ah, const u16* __restrict__ Al,
               const u16* __restrict__ Bh, const u16* __restrict__ Bl,
               const float* __restrict__ bias, int M_real,
               u16* __restrict__ oH, u16* __restrict__ oL,
               float* __restrict__ oF, int T) {
    constexpr int Kpad = KCH * 64;
    constexpr int TOTAL = 3 * KCH;
    __shared__ __align__(16) char smem[49152];   // A0 16K | B0 8K | A1 16K | B1 8K

    const int tid = threadIdx.x, lane = tid & 31, wid = tid >> 5;
    const int wm = wid & 3, wn = wid >> 2;       // 4 x 2 warp grid (32m x 32t each)
    const int mt = blockIdx.x, nt = blockIdx.y;
    const int scol = tid & 7;                    // staging uint4 column
    const int srow = tid >> 3;                   // staging row 0..31

    const int AO[2] = {0, 24576};
    const int BO[2] = {16384, 40960};

    // ldmatrix lane sub-addresses
    const int a_r  = lane & 15, a_c8 = (lane >> 4) * 8;
    const int b_t  = (lane & 7) + ((lane >> 4) << 3);
    const int b_k8 = ((lane >> 3) & 1) * 8;

    float c[8][4];
    #pragma unroll
    for (int i = 0; i < 8; i++)
        #pragma unroll
        for (int q = 0; q < 4; q++) c[i][q] = 0.f;

    // stage chunk 0 (pass 0 = Ah, Bh) into buffer 0
    #pragma unroll
    for (int j = 0; j < 4; j++) {
        uint4 v = *reinterpret_cast<const uint4*>(
            Ah + (size_t)(mt * 128 + srow + j * 32) * Kpad + scol * 8);
        *reinterpret_cast<uint4*>(smem + AO[0] + SWZ((srow + j * 32) * 128 + scol * 16)) = v;
    }
    #pragma unroll
    for (int j = 0; j < 2; j++) {
        int t = nt * 64 + srow + j * 32; if (t >= T) t = T - 1;
        uint4 v = *reinterpret_cast<const uint4*>(Bh + (size_t)t * Kpad + scol * 8);
        *reinterpret_cast<uint4*>(smem + BO[0] + SWZ((srow + j * 32) * 128 + scol * 16)) = v;
    }
    __syncthreads();

    const uint32_t sbase = smem_u32(smem);

    for (int ic = 0; ic < TOTAL; ic++) {
        const int buf = ic & 1;
        uint4 pa[4], pb[2];
        const bool nx = (ic + 1 < TOTAL);
        if (nx) {
            int icn = ic + 1, p = icn / KCH, kc = icn - p * KCH;
            const u16* Ap = (p == 2) ? Al : Ah;
            const u16* Bp = (p == 1) ? Bl : Bh;
            #pragma unroll
            for (int j = 0; j < 4; j++)
                pa[j] = *reinterpret_cast<const uint4*>(
                    Ap + (size_t)(mt * 128 + srow + j * 32) * Kpad + kc * 64 + scol * 8);
            #pragma unroll
            for (int j = 0; j < 2; j++) {
                int t = nt * 64 + srow + j * 32; if (t >= T) t = T - 1;
                pb[j] = *reinterpret_cast<const uint4*>(
                    Bp + (size_t)t * Kpad + kc * 64 + scol * 8);
            }
        }

        const uint32_t sa = sbase + AO[buf];
        const uint32_t sB = sbase + BO[buf];
        #pragma unroll
        for (int ks = 0; ks < 4; ks++) {
            uint32_t a0[4], a1[4], bA[4], bB[4];
            ldsm4(a0, sa + SWZ((wm * 32 + a_r) * 128 + (ks * 16 + a_c8) * 2));
            ldsm4(a1, sa + SWZ((wm * 32 + 16 + a_r) * 128 + (ks * 16 + a_c8) * 2));
            ldsm4(bA, sB + SWZ((wn * 32 + b_t) * 128 + (ks * 16 + b_k8) * 2));
            ldsm4(bB, sB + SWZ((wn * 32 + 16 + b_t) * 128 + (ks * 16 + b_k8) * 2));
            mma_bf16(c[0], a0, bA[0], bA[1]);
            mma_bf16(c[1], a0, bA[2], bA[3]);
            mma_bf16(c[2], a0, bB[0], bB[1]);
            mma_bf16(c[3], a0, bB[2], bB[3]);
            mma_bf16(c[4], a1, bA[0], bA[1]);
            mma_bf16(c[5], a1, bA[2], bA[3]);
            mma_bf16(c[6], a1, bB[0], bB[1]);
            mma_bf16(c[7], a1, bB[2], bB[3]);
        }

        if (nx) {
            const int nb = 1 - buf;
            #pragma unroll
            for (int j = 0; j < 4; j++)
                *reinterpret_cast<uint4*>(smem + AO[nb] + SWZ((srow + j * 32) * 128 + scol * 16)) = pa[j];
            #pragma unroll
            for (int j = 0; j < 2; j++)
                *reinterpret_cast<uint4*>(smem + BO[nb] + SWZ((srow + j * 32) * 128 + scol * 16)) = pb[j];
        }
        __syncthreads();
    }

    // epilogue: accum -> smem [m][t] (stride 66), then coalesced bias+relu+store
    float* sO = reinterpret_cast<float*>(smem);
    const int dr = lane >> 2, dc = 2 * (lane & 3);
    #pragma unroll
    for (int fm = 0; fm < 2; fm++)
        #pragma unroll
        for (int fn = 0; fn < 4; fn++) {
            const float* cc = c[fm * 4 + fn];
            int m0 = wm * 32 + fm * 16 + dr;
            int t0 = wn * 32 + fn * 8 + dc;
            sO[m0 * 66 + t0]           = cc[0];
            sO[m0 * 66 + t0 + 1]       = cc[1];
            sO[(m0 + 8) * 66 + t0]     = cc[2];
            sO[(m0 + 8) * 66 + t0 + 1] = cc[3];
        }
    __syncthreads();

    for (int i = tid; i < 128 * 64; i += 256) {
        int t = i >> 7, m = i & 127;
        int mg = mt * 128 + m, tg = nt * 64 + t;
        if (mg < M_real && tg < T) {
            float y = fmaxf(sO[m * 66 + t] + __ldg(bias + mg / 6), 0.f);
            if (MODE == 0) {
                u16 hh, ll;
                bsplit(y, hh, ll);
                oH[(size_t)tg * K2PAD + mg] = hh;
                oL[(size_t)tg * K2PAD + mg] = ll;
            } else {
                oF[(size_t)tg * K1PAD + mg] = y;
            }
        }
    }
}

// ---------------- BN statistics (fp64, 8 slices + atomics) -------------------------
__global__ void bn_stats(int T) {
    int n = blockIdx.x, slice = blockIdx.y, tid = threadIdx.x;
    int tpc = (T + gridDim.y - 1) / gridDim.y;
    int tlo = slice * tpc, thi = min(T, tlo + tpc);
    double s = 0.0, sq = 0.0;
    for (int t = tlo + tid; t < thi; t += blockDim.x) {
        const float* p = g_f3 + (size_t)t * K1PAD + n * 6;
        #pragma unroll
        for (int h = 0; h < HID; h++) { float v = p[h]; s += v; sq += (double)v * v; }
    }
    __shared__ double ss[256], ssq[256];
    ss[tid] = s; ssq[tid] = sq; __syncthreads();
    for (int k = 128; k > 0; k >>= 1) {
        if (tid < k) { ss[tid] += ss[tid + k]; ssq[tid] += ssq[tid + k]; }
        __syncthreads();
    }
    if (tid == 0) {
        atomicAdd(&g_sumd[n], ss[0]);
        atomicAdd(&g_sqd[n],  ssq[0]);
    }
}

__global__ void bn_finalize(const float* __restrict__ gamma,
                            const float* __restrict__ beta, int T) {
    int n = threadIdx.x;
    if (n >= N_NODES) return;
    double cnt  = (double)T * HID;
    double mean = g_sumd[n] / cnt;
    double var  = g_sqd[n] / cnt - mean * mean;
    float rstd  = (float)(1.0 / sqrt(var + 1e-5));
    float sc    = gamma[n] * rstd;
    g_scale[n]  = sc;
    g_shift[n]  = beta[n] - (float)mean * sc;
}

// ---------------- BN apply + 6x6 linear --------------------------------------------
__global__ void final_kernel(const float* __restrict__ Wl, const float* __restrict__ bl,
                             float* __restrict__ outp, int TN) {
    __shared__ float swl[HID * HID], sbl[HID], ssc[N_NODES], ssh[N_NODES];
    int tid = threadIdx.x;
    if (tid < HID * HID) swl[tid] = Wl[tid];
    if (tid < HID)       sbl[tid] = bl[tid];
    if (tid < N_NODES)  { ssc[tid] = g_scale[tid]; ssh[tid] = g_shift[tid]; }
    __syncthreads();
    int r = blockIdx.x * blockDim.x + tid;
    if (r >= TN) return;
    int t = r / 97, n = r - t * 97;
    const float* p = g_f3 + (size_t)t * K1PAD + n * 6;
    float v[HID];
    #pragma unroll
    for (int h = 0; h < HID; h++) v[h] = fmaf(p[h], ssc[n], ssh[n]);
    float* o = outp + (size_t)r * HID;
    #pragma unroll
    for (int j = 0; j < HID; j++) {
        float acc = sbl[j];
        #pragma unroll
        for (int k = 0; k < HID; k++) acc = fmaf(swl[j * HID + k], v[k], acc);
        o[j] = acc;
    }
}

// ---------------- launch -----------------------------------------------------------
extern "C" void kernel_launch(void* const* d_in, const int* in_sizes, int n_in,
                              void* d_out, int out_size) {
    const float* X    = (const float*)d_in[1];
    const float* W_ih = (const float*)d_in[3];
    const float* W_hh = (const float*)d_in[4];
    const float* b_ih = (const float*)d_in[5];
    const float* b_hh = (const float*)d_in[6];
    const float* Wc1  = (const float*)d_in[7];
    const float* bc1  = (const float*)d_in[8];
    const float* Wc2  = (const float*)d_in[9];
    const float* bc2  = (const float*)d_in[10];
    const float* Wc3  = (const float*)d_in[11];
    const float* bc3  = (const float*)d_in[12];
    const float* gamma= (const float*)d_in[13];
    const float* beta = (const float*)d_in[14];
    const float* Wl   = (const float*)d_in[15];
    const float* bl   = (const float*)d_in[16];

    int T  = in_sizes[1] / (N_NODES * IN_T);
    int TN = T * N_NODES;
    int NSEG = (T + SEG - 1) / SEG;
    int NT = (T + 63) / 64;

    u16 *a1h, *a1l, *a2h, *a2l, *a3h, *a3l, *b0h, *b0l, *f1h, *f1l, *f2h, *f2l;
    float* f3;
    cudaGetSymbolAddress((void**)&a1h, g_a1h); cudaGetSymbolAddress((void**)&a1l, g_a1l);
    cudaGetSymbolAddress((void**)&a2h, g_a2h); cudaGetSymbolAddress((void**)&a2l, g_a2l);
    cudaGetSymbolAddress((void**)&a3h, g_a3h); cudaGetSymbolAddress((void**)&a3l, g_a3l);
    cudaGetSymbolAddress((void**)&b0h, g_b0h); cudaGetSymbolAddress((void**)&b0l, g_b0l);
    cudaGetSymbolAddress((void**)&f1h, g_f1h); cudaGetSymbolAddress((void**)&f1l, g_f1l);
    cudaGetSymbolAddress((void**)&f2h, g_f2h); cudaGetSymbolAddress((void**)&f2l, g_f2l);
    cudaGetSymbolAddress((void**)&f3,  g_f3);

    prep_all<<<(1280 * K2PAD + 255) / 256, 256>>>(Wc1, Wc2, Wc3);
    xproj_kernel<<<(TN + 287) / 288, 288>>>(X, W_ih, b_ih, b_hh, TN);
    lstm_seg<<<NSEG * 5, 128>>>(W_hh, T);

    gemm_conv<10, 0><<<dim3(10, NT), 256>>>(a1h, a1l, b0h, b0l, bc1, 1164,
                                            f1h, f1l, nullptr, T);
    gemm_conv<19, 0><<<dim3(10, NT), 256>>>(a2h, a2l, f1h, f1l, bc2, 1164,
                                            f2h, f2l, nullptr, T);
    gemm_conv<19, 1><<<dim3(5, NT), 256>>>(a3h, a3l, f2h, f2l, bc3, 582,
                                           nullptr, nullptr, f3, T);

    bn_stats<<<dim3(N_NODES, 8), 256>>>(T);
    bn_finalize<<<1, 128>>>(gamma, beta, T);
    final_kernel<<<(TN + 255) / 256, 256>>>(Wl, bl, (float*)d_out, TN);
}